// round 14
// baseline (speedup 1.0000x reference)
#include <cuda_runtime.h>
#include <cuda_bf16.h>

// HOGLayer: img (32,1,512,512) f32 -> out (32, 158760) f32
#define NIMG   32
#define HH     512
#define WW     512
#define NB     10
#define HC     64          // cells per side
#define NBR    63          // HC - CPB + 1
#define NZ     (NIMG*NB)   // 320
#define RC     (NBR*NBR)   // 3969

// ---------------- device scratch ----------------
// zero-initialized at module load; zero_stats re-zeroes SS/MX after each use
__device__ float    g_pooled[NZ * HC * HC];   // (z, cy, cx)
__device__ float    g_SS [HC * HC];           // per-cell sum v^2 over z (atomic)
__device__ unsigned g_MXu[HC * HC];           // per-cell max v over z (bits, v>=0)

// ---------------- helpers ----------------
__device__ __forceinline__ float fsqrt_approx(float x) {
    float r; asm("sqrt.approx.f32 %0, %1;" : "=f"(r) : "f"(x)); return r;
}

// Sector classification: fi = floor(pbin) in 0..9 via two slope tests +
// integer reflections. Packed accumulator: acc[fi] += mag + 128
// (count = floor(acc/128), summag = acc - 128*count at reduction).
// Index-safety: ft in {0,1,2} -> ft1 in {0..4} -> fi in {0..9} always.
__device__ __forceinline__ void accum_pixel(float gx, float gy, float* bp) {
    float d2  = fmaf(gx, gx, gy * gy);
    float mag = fsqrt_approx(d2);

    float ax = fabsf(gy), ay = fabsf(gx);
    float mn = fminf(ax, ay), mx = fmaxf(ax, ay);
    int ft = (fmaf(-0.32491970f, mx, mn) > 0.0f)    // a > tan(pi/10)
           + (fmaf(-0.72654253f, mx, mn) > 0.0f);   // a > tan(pi/5)
    int ft1 = (ay > ax) ? 4 - ft : ft;              // pi/2 reflection
    bool c  = ((__float_as_int(gx) ^ __float_as_int(gy)) < 0);  // sign(gx)!=sign(gy)
    int fi  = c ? 9 - ft1 : ft1;                    // 0..9

    // stride 256: bank = tid%32 regardless of bin -> zero conflicts
    bp[fi << 8] += mag + 128.0f;
}

__device__ __forceinline__ void load6(float* V, const float* rp, int q) {
    if (rp) {
        float4 v4 = *reinterpret_cast<const float4*>(rp);
        V[1] = v4.x; V[2] = v4.y; V[3] = v4.z; V[4] = v4.w;
        V[0] = (q > 0)   ? __ldg(rp - 1) : 0.f;
        V[5] = (q < 127) ? __ldg(rp + 4) : 0.f;
    } else {
#pragma unroll
        for (int j = 0; j < 6; j++) V[j] = 0.f;
    }
}

// ---------------- kernel A: conv + histogram + pool + cell stats --------
// grid 2048 x 256: block = 1 cell-row of one image (64 cells).
// thread = 4-wide x 4-tall quarter-cell. Separable Sobel, rolling rows.
// (exact R12 form - the R13 shared-scratch tail regressed and is reverted)
__global__ void __launch_bounds__(256) hog_cells(const float* __restrict__ img) {
    __shared__ __align__(16) float bins[NB * 256];   // 10 KB
    const int tid = threadIdx.x;
    const int n   = blockIdx.x >> 6;
    const int cy  = blockIdx.x & 63;
    const int ry  = tid >> 7;            // top/bottom half of the cell
    const int q   = tid & 127;           // 128 quarter-columns
    const int x0  = q * 4;
    const int y0  = cy * 8 + ry * 4;
    const float* im = img + n * (HH * WW);

    // vectorized zero-init (cross-warp ownership -> barrier REQUIRED below)
    {
        float4* b4 = reinterpret_cast<float4*>(bins);
        const float4 z4 = make_float4(0.f, 0.f, 0.f, 0.f);
        b4[tid] = z4;
        b4[tid + 256] = z4;
        if (tid < 128) b4[tid + 512] = z4;
    }
    __syncthreads();
    float* bp = bins + tid;

    float P[6], Q[6], N[6];
    load6(P, (y0 > 0) ? (im + (y0 - 1) * WW + x0) : (const float*)0, q);
    load6(Q, im + y0 * WW + x0, q);

#pragma unroll
    for (int r = 0; r < 4; r++) {
        const int yy = y0 + 1 + r;
        load6(N, (yy < HH) ? (im + yy * WW + x0) : (const float*)0, q);

        float S[6], D[6];
#pragma unroll
        for (int j = 0; j < 6; j++) {
            float pn = P[j] + N[j];
            S[j] = fmaf(2.0f, Q[j], pn);   // vertical smooth
            D[j] = P[j] - N[j];            // vertical diff
        }
#pragma unroll
        for (int i = 0; i < 4; i++) {
            float gx = S[i] - S[i + 2];
            float gy = fmaf(2.0f, D[i + 1], D[i] + D[i + 2]);
            accum_pixel(gx, gy, bp);
        }
#pragma unroll
        for (int j = 0; j < 6; j++) { P[j] = Q[j]; Q[j] = N[j]; }
    }

    __syncthreads();

    // cell = threads {2cx, 2cx+1, 128+2cx, 129+2cx}; role rr covers bins rr, rr+4, rr+8
    // bin b = sum over 4 slots of: summag[b] + (count[b-1] - summag[b-1]), mod-10 wrap
    const int cx = q >> 1;
    const int rr = ry * 2 + (q & 1);
    const int t0 = 2 * cx;
    float ss = 0.0f, mxv = 0.0f;
#pragma unroll
    for (int b = rr; b < NB; b += 4) {
        const int bm = (b + 9) % 10;
        const float* rb = bins + (b  << 8);
        const float* rm = bins + (bm << 8);
        float s = 0.0f;
#pragma unroll
        for (int j0 = 0; j0 < 4; j0++) {
            const int off = t0 + (j0 & 1) + ((j0 >> 1) << 7);
            float Ab = rb[off], Am = rm[off];
            float cb = floorf(Ab * 0.0078125f);
            float sb = fmaf(cb, -128.0f, Ab);
            float cm = floorf(Am * 0.0078125f);
            float sm = fmaf(cm, -128.0f, Am);
            s += sb + (cm - sm);
        }
        s *= 0.015625f;
        g_pooled[((n * NB + b) * HC + cy) * HC + cx] = s;
        ss  = fmaf(s, s, ss);
        mxv = fmaxf(mxv, s);
    }

    // combine the two same-warp roles (adjacent lanes), then one atomic per
    // remaining pair: 2 atomicAdds + 2 atomicMaxs per cell total.
    ss  += __shfl_xor_sync(0xffffffffu, ss, 1);
    mxv  = fmaxf(mxv, __shfl_xor_sync(0xffffffffu, mxv, 1));
    if ((q & 1) == 0) {
        atomicAdd(&g_SS[cy * HC + cx], ss);
        atomicMax(&g_MXu[cy * HC + cx], __float_as_uint(mxv));
    }
}

// ---------------- kernel C: fused norms + normalized feature write ----
// grid (16, 160): blockIdx.y = n*5 + pair; thread = one r2, handling
// bins {2*pair, 2*pair+1} x 4 (i,j) = 8 outputs. 5x the blocks of the R12
// version -> ~full occupancy to hide L2 latency (R12 ran at ~43% occ).
__global__ void __launch_bounds__(256) write_out(float* __restrict__ out) {
    int r2 = blockIdx.x * 256 + threadIdx.x;
    if (r2 >= RC) return;
    const int n    = blockIdx.y / 5;
    const int pair = blockIdx.y - n * 5;
    const int b0   = pair * 2;
    const int r = r2 / NBR;
    const int c = r2 - r * NBR;
    const int c00 = r * HC + c;

    float s  = g_SS[c00] + g_SS[c00 + 1] + g_SS[c00 + HC] + g_SS[c00 + HC + 1];
    float mx = fmaxf(fmaxf(__uint_as_float(g_MXu[c00]),
                           __uint_as_float(g_MXu[c00 + 1])),
                     fmaxf(__uint_as_float(g_MXu[c00 + HC]),
                           __uint_as_float(g_MXu[c00 + HC + 1])));
    const float i1 = rsqrtf(s + 1e-10f);

    float s2;
    if (mx * i1 <= 0.2f) {
        s2 = s * i1 * i1;            // no element clamps: exact
    } else {
        s2 = 0.0f;                   // exact elementwise fallback (rare/slow)
        int cells[4] = {c00, c00 + 1, c00 + HC, c00 + HC + 1};
#pragma unroll
        for (int k = 0; k < 4; k++) {
            for (int z = 0; z < NZ; z++) {
                float w = fminf(g_pooled[z * (HC * HC) + cells[k]] * i1, 0.2f);
                s2 = fmaf(w, w, s2);
            }
        }
    }
    const float i2 = rsqrtf(s2 + 1e-10f);

    float pv[2][4];
#pragma unroll
    for (int e = 0; e < 2; e++) {
        const float* pb = g_pooled + ((n * NB + b0 + e) * HC + r) * HC + c;
        pv[e][0] = pb[0];
        pv[e][1] = pb[1];
        pv[e][2] = pb[HC];
        pv[e][3] = pb[HC + 1];
    }
#pragma unroll
    for (int e = 0; e < 2; e++) {
        float* ob = out + (n * NB + b0 + e) * (4 * RC) + r2;
#pragma unroll
        for (int k = 0; k < 4; k++)
            ob[k * RC] = fminf(pv[e][k] * i1, 0.2f) * i2;
    }
}

// ---------------- kernel D: re-zero the atomic stats for the next call --
__global__ void __launch_bounds__(256) zero_stats() {
    int i = blockIdx.x * 256 + threadIdx.x;
    g_SS[i]  = 0.0f;
    g_MXu[i] = 0u;
}

// ---------------- launcher ----------------
extern "C" void kernel_launch(void* const* d_in, const int* in_sizes, int n_in,
                              void* d_out, int out_size) {
    const float* img = (const float*)d_in[0];
    (void)in_sizes; (void)n_in; (void)out_size;

    hog_cells<<<2048, 256>>>(img);
    dim3 gw(16, NIMG * 5);
    write_out<<<gw, 256>>>((float*)d_out);
    zero_stats<<<HC * HC / 256, 256>>>();   // restores the load-time invariant
}

// round 15
// speedup vs baseline: 1.4545x; 1.4545x over previous
#include <cuda_runtime.h>
#include <cuda_bf16.h>

// HOGLayer: img (32,1,512,512) f32 -> out (32, 158760) f32
#define NIMG   32
#define HH     512
#define WW     512
#define NB     10
#define HC     64          // cells per side
#define NBR    63          // HC - CPB + 1
#define NZ     (NIMG*NB)   // 320
#define RC     (NBR*NBR)   // 3969

// ---------------- device scratch ----------------
// zero-initialized at module load; zero_stats re-zeroes SS/MX after each use
__device__ float    g_pooled[NZ * HC * HC];   // (z, cy, cx)
__device__ float    g_SS [HC * HC];           // per-cell sum v^2 over z (atomic)
__device__ unsigned g_MXu[HC * HC];           // per-cell max v over z (bits, v>=0)
__device__ float    g_inv1[RC];
__device__ float    g_inv2[RC];

// ---------------- helpers ----------------
__device__ __forceinline__ float fsqrt_approx(float x) {
    float r; asm("sqrt.approx.f32 %0, %1;" : "=f"(r) : "f"(x)); return r;
}

// Sector classification: fi = floor(pbin) in 0..9 via two slope tests +
// integer reflections. Packed accumulator: acc[fi] += mag + 128
// (count = floor(acc/128), summag = acc - 128*count at reduction).
// Index-safety: ft in {0,1,2} -> ft1 in {0..4} -> fi in {0..9} always.
__device__ __forceinline__ void accum_pixel(float gx, float gy, float* bp) {
    float d2  = fmaf(gx, gx, gy * gy);
    float mag = fsqrt_approx(d2);

    float ax = fabsf(gy), ay = fabsf(gx);
    float mn = fminf(ax, ay), mx = fmaxf(ax, ay);
    int ft = (fmaf(-0.32491970f, mx, mn) > 0.0f)    // a > tan(pi/10)
           + (fmaf(-0.72654253f, mx, mn) > 0.0f);   // a > tan(pi/5)
    int ft1 = (ay > ax) ? 4 - ft : ft;              // pi/2 reflection
    bool c  = ((__float_as_int(gx) ^ __float_as_int(gy)) < 0);  // sign(gx)!=sign(gy)
    int fi  = c ? 9 - ft1 : ft1;                    // 0..9

    // stride 256: bank = tid%32 regardless of bin -> zero conflicts
    bp[fi << 8] += mag + 128.0f;
}

__device__ __forceinline__ void load6(float* V, const float* rp, int q) {
    if (rp) {
        float4 v4 = *reinterpret_cast<const float4*>(rp);
        V[1] = v4.x; V[2] = v4.y; V[3] = v4.z; V[4] = v4.w;
        V[0] = (q > 0)   ? __ldg(rp - 1) : 0.f;
        V[5] = (q < 127) ? __ldg(rp + 4) : 0.f;
    } else {
#pragma unroll
        for (int j = 0; j < 6; j++) V[j] = 0.f;
    }
}

// ---------------- kernel A: conv + histogram + pool + cell stats --------
// grid 2048 x 256: block = 1 cell-row of one image (64 cells).
// thread = 4-wide x 4-tall quarter-cell. Separable Sobel, rolling rows.
// (exact R12 form)
__global__ void __launch_bounds__(256) hog_cells(const float* __restrict__ img) {
    __shared__ __align__(16) float bins[NB * 256];   // 10 KB
    const int tid = threadIdx.x;
    const int n   = blockIdx.x >> 6;
    const int cy  = blockIdx.x & 63;
    const int ry  = tid >> 7;            // top/bottom half of the cell
    const int q   = tid & 127;           // 128 quarter-columns
    const int x0  = q * 4;
    const int y0  = cy * 8 + ry * 4;
    const float* im = img + n * (HH * WW);

    // vectorized zero-init (cross-warp ownership -> barrier REQUIRED below)
    {
        float4* b4 = reinterpret_cast<float4*>(bins);
        const float4 z4 = make_float4(0.f, 0.f, 0.f, 0.f);
        b4[tid] = z4;
        b4[tid + 256] = z4;
        if (tid < 128) b4[tid + 512] = z4;
    }
    __syncthreads();
    float* bp = bins + tid;

    float P[6], Q[6], N[6];
    load6(P, (y0 > 0) ? (im + (y0 - 1) * WW + x0) : (const float*)0, q);
    load6(Q, im + y0 * WW + x0, q);

#pragma unroll
    for (int r = 0; r < 4; r++) {
        const int yy = y0 + 1 + r;
        load6(N, (yy < HH) ? (im + yy * WW + x0) : (const float*)0, q);

        float S[6], D[6];
#pragma unroll
        for (int j = 0; j < 6; j++) {
            float pn = P[j] + N[j];
            S[j] = fmaf(2.0f, Q[j], pn);   // vertical smooth
            D[j] = P[j] - N[j];            // vertical diff
        }
#pragma unroll
        for (int i = 0; i < 4; i++) {
            float gx = S[i] - S[i + 2];
            float gy = fmaf(2.0f, D[i + 1], D[i] + D[i + 2]);
            accum_pixel(gx, gy, bp);
        }
#pragma unroll
        for (int j = 0; j < 6; j++) { P[j] = Q[j]; Q[j] = N[j]; }
    }

    __syncthreads();

    // cell = threads {2cx, 2cx+1, 128+2cx, 129+2cx}; role rr covers bins rr, rr+4, rr+8
    // bin b = sum over 4 slots of: summag[b] + (count[b-1] - summag[b-1]), mod-10 wrap
    const int cx = q >> 1;
    const int rr = ry * 2 + (q & 1);
    const int t0 = 2 * cx;
    float ss = 0.0f, mxv = 0.0f;
#pragma unroll
    for (int b = rr; b < NB; b += 4) {
        const int bm = (b + 9) % 10;
        const float* rb = bins + (b  << 8);
        const float* rm = bins + (bm << 8);
        float s = 0.0f;
#pragma unroll
        for (int j0 = 0; j0 < 4; j0++) {
            const int off = t0 + (j0 & 1) + ((j0 >> 1) << 7);
            float Ab = rb[off], Am = rm[off];
            float cb = floorf(Ab * 0.0078125f);
            float sb = fmaf(cb, -128.0f, Ab);
            float cm = floorf(Am * 0.0078125f);
            float sm = fmaf(cm, -128.0f, Am);
            s += sb + (cm - sm);
        }
        s *= 0.015625f;
        g_pooled[((n * NB + b) * HC + cy) * HC + cx] = s;
        ss  = fmaf(s, s, ss);
        mxv = fmaxf(mxv, s);
    }

    ss  += __shfl_xor_sync(0xffffffffu, ss, 1);
    mxv  = fmaxf(mxv, __shfl_xor_sync(0xffffffffu, mxv, 1));
    if ((q & 1) == 0) {
        atomicAdd(&g_SS[cy * HC + cx], ss);
        atomicMax(&g_MXu[cy * HC + cx], __float_as_uint(mxv));
    }
}

// ---------------- kernel B: per-(r,c) L2-Hys inverse norms ----------------
// 16 blocks x 256: one thread per r2; tiny, L2-resident.
__global__ void __launch_bounds__(256) norm_stats() {
    int r2 = blockIdx.x * 256 + threadIdx.x;
    if (r2 >= RC) return;
    const int r = r2 / NBR;
    const int c = r2 - r * NBR;
    const int c00 = r * HC + c;

    float s  = g_SS[c00] + g_SS[c00 + 1] + g_SS[c00 + HC] + g_SS[c00 + HC + 1];
    float mx = fmaxf(fmaxf(__uint_as_float(g_MXu[c00]),
                           __uint_as_float(g_MXu[c00 + 1])),
                     fmaxf(__uint_as_float(g_MXu[c00 + HC]),
                           __uint_as_float(g_MXu[c00 + HC + 1])));
    const float i1 = rsqrtf(s + 1e-10f);

    float s2;
    if (mx * i1 <= 0.2f) {
        s2 = s * i1 * i1;            // no element clamps: exact
    } else {
        s2 = 0.0f;                   // exact elementwise fallback (rare/slow)
        int cells[4] = {c00, c00 + 1, c00 + HC, c00 + HC + 1};
#pragma unroll
        for (int k = 0; k < 4; k++) {
            for (int z = 0; z < NZ; z++) {
                float w = fminf(g_pooled[z * (HC * HC) + cells[k]] * i1, 0.2f);
                s2 = fmaf(w, w, s2);
            }
        }
    }
    g_inv1[r2] = i1;
    g_inv2[r2] = rsqrtf(s2 + 1e-10f);
}

// ---------------- kernel C: normalized feature write ----------------
// grid (16, 160): blockIdx.y = n*5 + pair; thread = one r2, bins
// {2*pair, 2*pair+1} x 4 (i,j) = 8 outputs. High occupancy; all loads
// (inv1/inv2/pooled) and stores coalesced across the warp.
__global__ void __launch_bounds__(256) write_out(float* __restrict__ out) {
    int r2 = blockIdx.x * 256 + threadIdx.x;
    if (r2 >= RC) return;
    const int n    = blockIdx.y / 5;
    const int pair = blockIdx.y - n * 5;
    const int b0   = pair * 2;
    const int r = r2 / NBR;
    const int c = r2 - r * NBR;

    const float i1 = g_inv1[r2];
    const float i2 = g_inv2[r2];

    float pv[2][4];
#pragma unroll
    for (int e = 0; e < 2; e++) {
        const float* pb = g_pooled + ((n * NB + b0 + e) * HC + r) * HC + c;
        pv[e][0] = pb[0];
        pv[e][1] = pb[1];
        pv[e][2] = pb[HC];
        pv[e][3] = pb[HC + 1];
    }
#pragma unroll
    for (int e = 0; e < 2; e++) {
        float* ob = out + (n * NB + b0 + e) * (4 * RC) + r2;
#pragma unroll
        for (int k = 0; k < 4; k++)
            ob[k * RC] = fminf(pv[e][k] * i1, 0.2f) * i2;
    }
}

// ---------------- kernel D: re-zero the atomic stats for the next call --
__global__ void __launch_bounds__(256) zero_stats() {
    int i = blockIdx.x * 256 + threadIdx.x;
    g_SS[i]  = 0.0f;
    g_MXu[i] = 0u;
}

// ---------------- launcher ----------------
extern "C" void kernel_launch(void* const* d_in, const int* in_sizes, int n_in,
                              void* d_out, int out_size) {
    const float* img = (const float*)d_in[0];
    (void)in_sizes; (void)n_in; (void)out_size;

    hog_cells<<<2048, 256>>>(img);
    norm_stats<<<16, 256>>>();
    dim3 gw(16, NIMG * 5);
    write_out<<<gw, 256>>>((float*)d_out);
    zero_stats<<<HC * HC / 256, 256>>>();   // restores the load-time invariant
}